// round 13
// baseline (speedup 1.0000x reference)
#include <cuda_runtime.h>
#include <cuda_fp16.h>
#include <cstdint>
#include <cstddef>

#define N_PTS 32768
#define HID   256
#define KTEST 1024
#define PI_F  3.14159274101257324f

// ---------------- global scratch ----------------
// Jet buffers, fp16 hi/lo planes: index ((m*3 + ch)*2 + hl)*256 + k
__device__ __half g_jetA[(size_t)N_PTS * 3 * 2 * HID];
__device__ __half g_jetB[(size_t)N_PTS * 3 * 2 * HID];
__device__ float g_part[(size_t)N_PTS * 16];
__device__ float g_r[N_PTS];
__device__ float g_Sp[8 * KTEST];
__device__ float g_ub[2];

// ---------------- math helpers ----------------
__device__ __forceinline__ float frcp(float x) {
    float r;
    asm("rcp.approx.f32 %0, %1;" : "=f"(r) : "f"(x));
    return r;
}

__device__ __forceinline__ void tanh4(const float* z, float* h) {
    float e[4], ep[4];
#pragma unroll
    for (int i = 0; i < 4; i++) {
        float zc = fminf(fmaxf(z[i], -9.0f), 9.0f);
        e[i]  = __expf(2.0f * zc);
        ep[i] = e[i] + 1.0f;
    }
    float p01   = ep[0] * ep[1];
    float p012  = p01 * ep[2];
    float p0123 = p012 * ep[3];
    float r = frcp(p0123);
    float i3 = p012 * r;  r *= ep[3];
    float i2 = p01  * r;  r *= ep[2];
    float i1 = ep[0] * r; r *= ep[1];
    float i0 = r;
    h[0] = (e[0] - 1.0f) * i0;
    h[1] = (e[1] - 1.0f) * i1;
    h[2] = (e[2] - 1.0f) * i2;
    h[3] = (e[3] - 1.0f) * i3;
}

__device__ __forceinline__ float my_sin(float a) {
    const float INV_PI = 0.3183098861837907f;
    float n = rintf(a * INV_PI);
    float r = fmaf(n, -3.14159274101257324f, a);
    r = fmaf(n, 8.742277657347586e-8f, r);
    float s2 = r * r;
    float p = -2.50521084e-8f;
    p = fmaf(p, s2, 2.75573192e-6f);
    p = fmaf(p, s2, -1.98412698e-4f);
    p = fmaf(p, s2, 8.33333333e-3f);
    p = fmaf(p, s2, -1.66666667e-1f);
    float s = fmaf(p * s2, r, r);
    return (((int)n) & 1) ? -s : s;
}

__device__ __forceinline__ void hsplit(float v, __half& hi, __half& lo) {
    hi = __float2half_rn(v);
    lo = __float2half_rn(v - __half2float(hi));
}

// fp16 HMMA (sm_80+ PTX).
__device__ __forceinline__ void mma16816(float* d, const uint32_t* a, const uint32_t* b) {
    asm volatile(
        "mma.sync.aligned.m16n8k16.row.col.f32.f16.f16.f32 "
        "{%0,%1,%2,%3}, {%4,%5,%6,%7}, {%8,%9}, {%0,%1,%2,%3};"
        : "+f"(d[0]), "+f"(d[1]), "+f"(d[2]), "+f"(d[3])
        : "r"(a[0]), "r"(a[1]), "r"(a[2]), "r"(a[3]), "r"(b[0]), "r"(b[1]));
}

// ldmatrix x4 (sm_75+ PTX).
__device__ __forceinline__ void ldsm4(uint32_t* r, uint32_t addr) {
    asm volatile("ldmatrix.sync.aligned.m8n8.x4.shared.b16 {%0,%1,%2,%3}, [%4];"
        : "=r"(r[0]), "=r"(r[1]), "=r"(r[2]), "=r"(r[3]) : "r"(addr));
}

__device__ __forceinline__ uint32_t smem_u32(const void* p) {
    uint32_t a;
    asm("{ .reg .u64 t; cvta.to.shared.u64 t, %1; cvt.u32.u64 %0, t; }" : "=r"(a) : "l"(p));
    return a;
}

// ---------------- SMEM geometry (fp16 elements) ----------------
// B: one K=128 half at a time (restaged once): 64 rows x 136 stride, hi+lo.
#define SB_E    136
#define BLO_E   8704                  // 64*136
#define AB_E    17408                 // A ring start (el)
// A: 64 rows x K=16 unpadded tiles with XOR-16B swizzle; 6 planes per chunk.
#define TILE_E  1024                  // 64*16
#define ASLOT_E (6 * TILE_E)          // 6144 el = 12288 B per ring slot
#define NBUF    4
#define SMEM_TOT ((AB_E + NBUF * ASLOT_E) * 2)   // 83968 B -> 2 CTAs/SM

// ---------------- MMA compute for one K=16 chunk (warp tile 16x32) ----------------
__device__ __forceinline__ void compute_chunk(
    uint32_t smb, int abuf, int kb,
    int wm, int wn, int lane, float acc[3][4][4])
{
    const int t  = lane >> 3, ri = lane & 7;

    // B: one x4 per nf -> {bh0, bh1, bl0, bl1} (lanes t>=2 address lo plane)
    uint32_t bh[4][2], bl[4][2];
#pragma unroll
    for (int nf = 0; nf < 4; nf++) {
        int n = wn * 32 + nf * 8 + ri;
        uint32_t el = ((t >> 1) ? BLO_E : 0) + n * SB_E + kb + (t & 1) * 8;
        uint32_t rg[4];
        ldsm4(rg, smb + el * 2);
        bh[nf][0] = rg[0]; bh[nf][1] = rg[1];
        bl[nf][0] = rg[2]; bl[nf][1] = rg[3];
    }

    const uint32_t aBase = AB_E + abuf * ASLOT_E;
    const int rr = wm * 16 + (t & 1) * 8 + ri;
    const int s  = t >> 1;
    const uint32_t sw = (uint32_t)((s ^ ((rr >> 2) & 1)) << 3);
#pragma unroll
    for (int ch = 0; ch < 3; ch++) {
        uint32_t ah[4], al[4];
        uint32_t eh  = aBase + (ch * 2 + 0) * TILE_E + rr * 16 + sw;
        uint32_t el2 = aBase + (ch * 2 + 1) * TILE_E + rr * 16 + sw;
        ldsm4(ah, smb + eh * 2);
        ldsm4(al, smb + el2 * 2);
#pragma unroll
        for (int nf = 0; nf < 4; nf++)
            mma16816(acc[ch][nf], ah, bh[nf]);   // hi*hi
#pragma unroll
        for (int nf = 0; nf < 4; nf++)
            mma16816(acc[ch][nf], ah, bl[nf]);   // hi*lo
#pragma unroll
        for (int nf = 0; nf < 4; nf++)
            mma16816(acc[ch][nf], al, bh[nf]);   // lo*hi
    }
}

// cp.async prefetch of one K=16 A-chunk (12 KB, 64 rows) into ring slot c%4.
__device__ __forceinline__ void issue_chunk(uint32_t smb, const __half* jin,
                                            int m0, int c, int tid) {
    const int kc = c * 16;
    const uint32_t dbase = smb + (uint32_t)(AB_E + (c % NBUF) * ASLOT_E) * 2;
#pragma unroll
    for (int it = 0; it < 3; it++) {
        int e = tid + it * 256;          // 0..767
        int t = e >> 7, rem = e & 127;
        int r = rem >> 1, s = rem & 1;
        const __half* src = jin
            + (((size_t)((m0 + r) * 3 + (t >> 1)) * 2 + (t & 1)) << 8) + kc + s * 8;
        uint32_t sw = (uint32_t)((s ^ ((r >> 2) & 1)) << 3);
        uint32_t dst = dbase + (uint32_t)(t * TILE_E + r * 16 + sw) * 2;
        unsigned long long gsrc = (unsigned long long)__cvta_generic_to_global(src);
        asm volatile("cp.async.cg.shared.global [%0], [%1], 16;" :: "r"(dst), "l"(gsrc) : "memory");
    }
    asm volatile("cp.async.commit_group;" ::: "memory");
}

// Stage one K=128 half of B = W^T (fp16 hi/lo split), n tile = 64 cols.
__device__ __forceinline__ void stage_B(__half* sm, const float* __restrict__ W,
                                        int n0, int k0, int tid) {
#pragma unroll
    for (int it = 0; it < 8; it++) {
        int e = tid + it * 256;
        int k = e >> 4, n4 = e & 15;
        float4 v = *(const float4*)(W + (size_t)(k0 + k) * HID + n0 + n4 * 4);
        float vv[4] = {v.x, v.y, v.z, v.w};
#pragma unroll
        for (int u = 0; u < 4; u++) {
            __half hh, ll; hsplit(vv[u], hh, ll);
            int off = (n4 * 4 + u) * SB_E + k;
            sm[off]         = hh;
            sm[BLO_E + off] = ll;
        }
    }
}

// ---------------- layer-0 jet init (fp16 hi/lo planes) ----------------
__global__ __launch_bounds__(256) void k_init(const float* __restrict__ x,
                                              const float* __restrict__ W0,
                                              const float* __restrict__ b0) {
    int gid = blockIdx.x * 256 + threadIdx.x;
    int m  = gid >> 6;
    int k  = (gid & 63) << 2;
    float xm = __ldg(x + m);
    float z[4], w[4], h[4];
#pragma unroll
    for (int u = 0; u < 4; u++) {
        w[u] = __ldg(W0 + k + u);
        z[u] = fmaf(xm, w[u], __ldg(b0 + k + u));
    }
    tanh4(z, h);
    __half st[3][2][4];
#pragma unroll
    for (int u = 0; u < 4; u++) {
        float g  = fmaf(-h[u], h[u], 1.0f);
        float d  = g * w[u];
        float e2 = -2.0f * h[u] * g * w[u] * w[u];
        hsplit(h[u], st[0][0][u], st[0][1][u]);
        hsplit(d,    st[1][0][u], st[1][1][u]);
        hsplit(e2,   st[2][0][u], st[2][1][u]);
    }
#pragma unroll
    for (int ch = 0; ch < 3; ch++)
#pragma unroll
        for (int hl = 0; hl < 2; hl++)
            *(uint2*)(g_jetA + (((size_t)(m * 3 + ch) * 2 + hl) << 8) + k)
                = *(uint2*)st[ch][hl];
}

// ---------------- fused hidden layer (CTA 64m x 64n, warp tile 16x32) ----------------
template<int WRITE_JET>
__global__ __launch_bounds__(256, 2) void k_layer(
    const __half* __restrict__ jin, __half* __restrict__ jout,
    const float* __restrict__ W, const float* __restrict__ bias,
    const float* __restrict__ W3)
{
    extern __shared__ __half sm[];
    const int tid = threadIdx.x, lane = tid & 31, wid = tid >> 5;
    const int wm = wid & 3, wn = wid >> 2;
    const int lg = lane >> 2, lq = lane & 3;
    const int nt = blockIdx.x & 3, mt = blockIdx.x >> 2;
    const int m0 = mt * 64, n0 = nt * 64;

    const uint32_t smb = smem_u32(sm);
    issue_chunk(smb, jin, m0, 0, tid);
    issue_chunk(smb, jin, m0, 1, tid);
    issue_chunk(smb, jin, m0, 2, tid);
    stage_B(sm, W, n0, 0, tid);

    float acc[3][4][4];
#pragma unroll
    for (int ch = 0; ch < 3; ch++)
#pragma unroll
        for (int nf = 0; nf < 4; nf++)
#pragma unroll
            for (int rr = 0; rr < 4; rr++) acc[ch][nf][rr] = 0.f;

    // ---- 16 chunks of K=16, 4-deep cp.async ring (3 ahead), B restaged at c=8 ----
    for (int c = 0; c < 16; c++) {
        if (c < 14)      { asm volatile("cp.async.wait_group 2;" ::: "memory"); }
        else if (c == 14){ asm volatile("cp.async.wait_group 1;" ::: "memory"); }
        else             { asm volatile("cp.async.wait_group 0;" ::: "memory"); }
        __syncthreads();   // chunk c visible to all warps; compute c-1 done
        if (c == 8) {
            stage_B(sm, W, n0, 128, tid);
            __syncthreads();
        }
        if (c + 3 < 16) issue_chunk(smb, jin, m0, c + 3, tid);
        compute_chunk(smb, c % NBUF, (c & 7) * 16, wm, wn, lane, acc);
    }

    // ---- epilogue ----
    if (WRITE_JET) {
#pragma unroll
        for (int rh = 0; rh < 2; rh++) {
            const int row = m0 + wm * 16 + rh * 8 + lg;
            float zz[8], aa[8], cc[8], hh[8];
#pragma unroll
            for (int nf = 0; nf < 4; nf++)
#pragma unroll
                for (int u = 0; u < 2; u++) {
                    const int e = nf * 2 + u;
                    const int col = n0 + wn * 32 + nf * 8 + lq * 2 + u;
                    zz[e] = acc[0][nf][rh * 2 + u] + __ldg(bias + col);
                    aa[e] = acc[1][nf][rh * 2 + u];
                    cc[e] = acc[2][nf][rh * 2 + u];
                }
            tanh4(zz, hh);
            tanh4(zz + 4, hh + 4);
#pragma unroll
            for (int nf = 0; nf < 4; nf++) {
                const int col = n0 + wn * 32 + nf * 8 + lq * 2;
                const int e0 = nf * 2, e1 = nf * 2 + 1;
                float h0 = hh[e0], h1 = hh[e1];
                float g0 = fmaf(-h0, h0, 1.0f), g1 = fmaf(-h1, h1, 1.0f);
                float d0 = g0 * aa[e0], d1 = g1 * aa[e1];
                float ev0 = g0 * fmaf(-2.0f * h0 * aa[e0], aa[e0], cc[e0]);
                float ev1 = g1 * fmaf(-2.0f * h1 * aa[e1], aa[e1], cc[e1]);
                float vs[3][2] = {{h0, h1}, {d0, d1}, {ev0, ev1}};
#pragma unroll
                for (int ch = 0; ch < 3; ch++) {
                    __half hA, lA, hB, lB;
                    hsplit(vs[ch][0], hA, lA);
                    hsplit(vs[ch][1], hB, lB);
                    __half2 hp = __halves2half2(hA, hB);
                    __half2 lp = __halves2half2(lA, lB);
                    *(uint32_t*)(jout + (((size_t)(row * 3 + ch) * 2 + 0) << 8) + col) = *(uint32_t*)&hp;
                    *(uint32_t*)(jout + (((size_t)(row * 3 + ch) * 2 + 1) << 8) + col) = *(uint32_t*)&lp;
                }
            }
        }
    } else {
        float su[2] = {0.f, 0.f};
        float se[2] = {0.f, 0.f};
#pragma unroll
        for (int rh = 0; rh < 2; rh++) {
            float zz[8], aa[8], cc[8], hh[8];
#pragma unroll
            for (int nf = 0; nf < 4; nf++)
#pragma unroll
                for (int u = 0; u < 2; u++) {
                    const int e = nf * 2 + u;
                    const int col = n0 + wn * 32 + nf * 8 + lq * 2 + u;
                    zz[e] = acc[0][nf][rh * 2 + u] + __ldg(bias + col);
                    aa[e] = acc[1][nf][rh * 2 + u];
                    cc[e] = acc[2][nf][rh * 2 + u];
                }
            tanh4(zz, hh);
            tanh4(zz + 4, hh + 4);
#pragma unroll
            for (int nf = 0; nf < 4; nf++) {
                const int col = n0 + wn * 32 + nf * 8 + lq * 2;
                const int e0 = nf * 2, e1 = nf * 2 + 1;
                float h0 = hh[e0], h1 = hh[e1];
                float g0 = fmaf(-h0, h0, 1.0f), g1 = fmaf(-h1, h1, 1.0f);
                float ev0 = g0 * fmaf(-2.0f * h0 * aa[e0], aa[e0], cc[e0]);
                float ev1 = g1 * fmaf(-2.0f * h1 * aa[e1], aa[e1], cc[e1]);
                float w30 = __ldg(W3 + col), w31 = __ldg(W3 + col + 1);
                su[rh] = fmaf(h0, w30, fmaf(h1, w31, su[rh]));
                se[rh] = fmaf(ev0, w30, fmaf(ev1, w31, se[rh]));
            }
        }
#pragma unroll
        for (int rh = 0; rh < 2; rh++) {
            float s = su[rh];
            s += __shfl_xor_sync(0xffffffffu, s, 1);
            s += __shfl_xor_sync(0xffffffffu, s, 2);
            float t = se[rh];
            t += __shfl_xor_sync(0xffffffffu, t, 1);
            t += __shfl_xor_sync(0xffffffffu, t, 2);
            if (lq == 0) {
                const int row = m0 + wm * 16 + rh * 8 + lg;
                const int p = nt * 2 + wn;
                g_part[(size_t)row * 16 + p]     = s;
                g_part[(size_t)row * 16 + 8 + p] = t;
            }
        }
    }
}

// ---------------- tiny kernels ----------------
__global__ void k_dummy() {}

__global__ void k_head(const float* __restrict__ x, const float* __restrict__ wts,
                       const float* __restrict__ b3) {
    int i = blockIdx.x * 256 + threadIdx.x;
    const float* p = g_part + (size_t)i * 16;
    float4 a0 = *(const float4*)p,       a1 = *(const float4*)(p + 4);
    float4 a2 = *(const float4*)(p + 8), a3 = *(const float4*)(p + 12);
    float su = ((a0.x + a0.y) + (a0.z + a0.w)) + ((a1.x + a1.y) + (a1.z + a1.w));
    float se = ((a2.x + a2.y) + (a2.z + a2.w)) + ((a3.x + a3.y) + (a3.z + a3.w));
    float xi = x[i];
    g_r[i] = wts[i] * (se + my_sin(PI_F * xi));
    if (i == 0)         g_ub[0] = su + __ldg(b3);
    if (i == N_PTS - 1) g_ub[1] = su + __ldg(b3);
}

__global__ __launch_bounds__(256) void k_spec(const float* __restrict__ x) {
    const int kg  = blockIdx.x >> 3;
    const int seg = blockIdx.x & 7;
    const int k0  = kg * 8;
    const int i0  = seg * 4096;
    float pk[8];
#pragma unroll
    for (int q = 0; q < 8; q++) pk[q] = PI_F * (float)(k0 + 1 + q);
    float acc[8] = {0, 0, 0, 0, 0, 0, 0, 0};
    for (int i = threadIdx.x; i < 4096; i += 256) {
        float xi = x[i0 + i], ri = g_r[i0 + i];
#pragma unroll
        for (int q = 0; q < 8; q++)
            acc[q] = fmaf(my_sin(pk[q] * xi), ri, acc[q]);
    }
    __shared__ float sred[8][8];
    int lane = threadIdx.x & 31, wid = threadIdx.x >> 5;
#pragma unroll
    for (int q = 0; q < 8; q++) {
        float v = acc[q];
#pragma unroll
        for (int o = 16; o; o >>= 1) v += __shfl_down_sync(0xffffffffu, v, o);
        if (lane == 0) sred[q][wid] = v;
    }
    __syncthreads();
    if (threadIdx.x < 8) {
        float s = 0.f;
#pragma unroll
        for (int w = 0; w < 8; w++) s += sred[threadIdx.x][w];
        g_Sp[seg * KTEST + k0 + threadIdx.x] = s;
    }
}

__global__ void k_final(float* __restrict__ out) {
    __shared__ float sred[8];
    float s = 0.f;
    for (int t = threadIdx.x; t < KTEST; t += 256) {
        float v = 0.f;
#pragma unroll
        for (int seg = 0; seg < 8; seg++) v += g_Sp[seg * KTEST + t];
        s = fmaf(v, v, s);
    }
    int lane = threadIdx.x & 31, wid = threadIdx.x >> 5;
#pragma unroll
    for (int o = 16; o; o >>= 1) s += __shfl_down_sync(0xffffffffu, s, o);
    if (lane == 0) sred[wid] = s;
    __syncthreads();
    if (threadIdx.x == 0) {
        float t = 0.f;
#pragma unroll
        for (int w = 0; w < 8; w++) t += sred[w];
        out[0] = t * (1.0f / 1024.0f);
        out[1] = 5.0f * (g_ub[0] * g_ub[0] + g_ub[1] * g_ub[1]);
    }
}

extern "C" void kernel_launch(void* const* d_in, const int* in_sizes, int n_in,
                              void* d_out, int out_size) {
    const float* x   = (const float*)d_in[0];
    const float* wts = (const float*)d_in[1];
    const float* W0  = (const float*)d_in[2];
    const float* b0  = (const float*)d_in[3];
    const float* W1  = (const float*)d_in[4];
    const float* b1  = (const float*)d_in[5];
    const float* W2  = (const float*)d_in[6];
    const float* b2  = (const float*)d_in[7];
    const float* W3  = (const float*)d_in[8];
    const float* b3  = (const float*)d_in[9];

    void *pA = nullptr, *pB = nullptr;
    cudaGetSymbolAddress(&pA, g_jetA);
    cudaGetSymbolAddress(&pB, g_jetB);
    __half* jA = (__half*)pA;
    __half* jB = (__half*)pB;

    cudaFuncSetAttribute(k_layer<1>, cudaFuncAttributeMaxDynamicSharedMemorySize, SMEM_TOT);
    cudaFuncSetAttribute(k_layer<0>, cudaFuncAttributeMaxDynamicSharedMemorySize, SMEM_TOT);

    k_dummy   <<<1, 32>>>();   // shifts ncu -s window onto a layer kernel
    k_init    <<<N_PTS * 64 / 256, 256>>>(x, W0, b0);
    k_layer<1><<<2048, 256, SMEM_TOT>>>(jA, jB, W1, b1, nullptr);
    k_layer<0><<<2048, 256, SMEM_TOT>>>(jB, nullptr, W2, b2, W3);
    k_head    <<<N_PTS / 256, 256>>>(x, wts, b3);
    k_spec    <<<KTEST, 256>>>(x);
    k_final   <<<1, 256>>>((float*)d_out);
}

// round 14
// speedup vs baseline: 1.2953x; 1.2953x over previous
#include <cuda_runtime.h>
#include <cuda_fp16.h>
#include <cstdint>
#include <cstddef>

#define N_PTS 32768
#define HID   256
#define KTEST 1024
#define PI_F  3.14159274101257324f

// ---------------- global scratch ----------------
// Fragment-major jets: [mt16(2048)][ch(3)][hl(2)][kt(16)][lane(32)] x uint4.
__device__ uint4 g_jetA[(size_t)2048 * 3 * 2 * 16 * 32];
__device__ uint4 g_jetB[(size_t)2048 * 3 * 2 * 16 * 32];
__device__ float g_part[(size_t)N_PTS * 16];
__device__ float g_r[N_PTS];
__device__ float g_Sp[8 * KTEST];
__device__ float g_ub[2];

// ---------------- math helpers ----------------
__device__ __forceinline__ float frcp(float x) {
    float r;
    asm("rcp.approx.f32 %0, %1;" : "=f"(r) : "f"(x));
    return r;
}

__device__ __forceinline__ void tanh4(const float* z, float* h) {
    float e[4], ep[4];
#pragma unroll
    for (int i = 0; i < 4; i++) {
        float zc = fminf(fmaxf(z[i], -9.0f), 9.0f);
        e[i]  = __expf(2.0f * zc);
        ep[i] = e[i] + 1.0f;
    }
    float p01   = ep[0] * ep[1];
    float p012  = p01 * ep[2];
    float p0123 = p012 * ep[3];
    float r = frcp(p0123);
    float i3 = p012 * r;  r *= ep[3];
    float i2 = p01  * r;  r *= ep[2];
    float i1 = ep[0] * r; r *= ep[1];
    float i0 = r;
    h[0] = (e[0] - 1.0f) * i0;
    h[1] = (e[1] - 1.0f) * i1;
    h[2] = (e[2] - 1.0f) * i2;
    h[3] = (e[3] - 1.0f) * i3;
}

__device__ __forceinline__ float my_sin(float a) {
    const float INV_PI = 0.3183098861837907f;
    float n = rintf(a * INV_PI);
    float r = fmaf(n, -3.14159274101257324f, a);
    r = fmaf(n, 8.742277657347586e-8f, r);
    float s2 = r * r;
    float p = -2.50521084e-8f;
    p = fmaf(p, s2, 2.75573192e-6f);
    p = fmaf(p, s2, -1.98412698e-4f);
    p = fmaf(p, s2, 8.33333333e-3f);
    p = fmaf(p, s2, -1.66666667e-1f);
    float s = fmaf(p * s2, r, r);
    return (((int)n) & 1) ? -s : s;
}

__device__ __forceinline__ void hsplit(float v, __half& hi, __half& lo) {
    hi = __float2half_rn(v);
    lo = __float2half_rn(v - __half2float(hi));
}

__device__ __forceinline__ uint32_t pack2(__half a, __half b) {
    __half2 t = __halves2half2(a, b);
    return *(uint32_t*)&t;
}

// fp16 HMMA (sm_80+ PTX).
__device__ __forceinline__ void mma16816(float* d, const uint32_t* a, const uint32_t* b) {
    asm volatile(
        "mma.sync.aligned.m16n8k16.row.col.f32.f16.f16.f32 "
        "{%0,%1,%2,%3}, {%4,%5,%6,%7}, {%8,%9}, {%0,%1,%2,%3};"
        : "+f"(d[0]), "+f"(d[1]), "+f"(d[2]), "+f"(d[3])
        : "r"(a[0]), "r"(a[1]), "r"(a[2]), "r"(a[3]), "r"(b[0]), "r"(b[1]));
}

// ldmatrix x4 (sm_75+ PTX).
__device__ __forceinline__ void ldsm4(uint32_t* r, uint32_t addr) {
    asm volatile("ldmatrix.sync.aligned.m8n8.x4.shared.b16 {%0,%1,%2,%3}, [%4];"
        : "=r"(r[0]), "=r"(r[1]), "=r"(r[2]), "=r"(r[3]) : "r"(addr));
}

__device__ __forceinline__ uint32_t smem_u32(const void* p) {
    uint32_t a;
    asm("{ .reg .u64 t; cvta.to.shared.u64 t, %1; cvt.u32.u64 %0, t; }" : "=r"(a) : "l"(p));
    return a;
}

// ---------------- SMEM geometry: B only (fp16 elements) ----------------
#define SB_E    136
#define BLO_E   8704                   // 64*136
#define SMEM_TOT (2 * 8704 * 2)        // 34816 B

// jet index (in uint4 units)
__device__ __forceinline__ size_t jidx(int mt16, int ch, int hl, int kt, int lane) {
    return ((((size_t)mt16 * 3 + ch) * 2 + hl) * 16 + kt) * 32 + lane;
}

// Stage one K=128 half of B = W^T (fp16 hi/lo split), n tile = 64 cols.
__device__ __forceinline__ void stage_B(__half* sm, const float* __restrict__ W,
                                        int n0, int k0, int tid) {
#pragma unroll
    for (int it = 0; it < 8; it++) {
        int e = tid + it * 256;
        int k = e >> 4, n4 = e & 15;
        float4 v = *(const float4*)(W + (size_t)(k0 + k) * HID + n0 + n4 * 4);
        float vv[4] = {v.x, v.y, v.z, v.w};
#pragma unroll
        for (int u = 0; u < 4; u++) {
            __half hh, ll; hsplit(vv[u], hh, ll);
            int off = (n4 * 4 + u) * SB_E + k;
            sm[off]         = hh;
            sm[BLO_E + off] = ll;
        }
    }
}

__device__ __forceinline__ void load_A(uint4* dst, const uint4* __restrict__ jin,
                                       int mt16, int kt, int lane) {
#pragma unroll
    for (int ch = 0; ch < 3; ch++)
#pragma unroll
        for (int hl = 0; hl < 2; hl++)
            dst[ch * 2 + hl] = __ldg(jin + jidx(mt16, ch, hl, kt, lane));
}

// ---------------- layer-0 jet init (fragment-major) ----------------
__global__ __launch_bounds__(256) void k_init(const float* __restrict__ x,
                                              const float* __restrict__ W0,
                                              const float* __restrict__ b0,
                                              uint4* __restrict__ jout) {
    int gid = blockIdx.x * 256 + threadIdx.x;   // 1,048,576 threads
    int tile = gid >> 5, lane = gid & 31;
    int mt16 = tile >> 4, kt = tile & 15;
    int lg = lane >> 2, lq = lane & 3;

    float x0 = __ldg(x + mt16 * 16 + lg);
    float x1 = __ldg(x + mt16 * 16 + lg + 8);
    int kc[4] = {kt * 16 + 2 * lq, kt * 16 + 2 * lq + 1,
                 kt * 16 + 2 * lq + 8, kt * 16 + 2 * lq + 9};
    float w[4], b[4];
#pragma unroll
    for (int c = 0; c < 4; c++) { w[c] = __ldg(W0 + kc[c]); b[c] = __ldg(b0 + kc[c]); }

    // e index: e = r*4 + c (r: row lg / lg+8; c: the 4 cols above)
    float z[8], h[8];
#pragma unroll
    for (int c = 0; c < 4; c++) {
        z[c]     = fmaf(x0, w[c], b[c]);
        z[4 + c] = fmaf(x1, w[c], b[c]);
    }
    tanh4(z, h);
    tanh4(z + 4, h + 4);

    __half VH[3][8], VL[3][8];
#pragma unroll
    for (int e = 0; e < 8; e++) {
        int c = e & 3;
        float hv = h[e];
        float g  = fmaf(-hv, hv, 1.0f);
        float d  = g * w[c];
        float e2 = -2.0f * hv * g * w[c] * w[c];
        hsplit(hv, VH[0][e], VL[0][e]);
        hsplit(d,  VH[1][e], VL[1][e]);
        hsplit(e2, VH[2][e], VL[2][e]);
    }
#pragma unroll
    for (int ch = 0; ch < 3; ch++)
#pragma unroll
        for (int hl = 0; hl < 2; hl++) {
            const __half* A = hl ? VL[ch] : VH[ch];
            uint4 o;
            o.x = pack2(A[0], A[1]);   // row lg,  cols 2lq,2lq+1   -> a0
            o.y = pack2(A[4], A[5]);   // row lg+8, same cols       -> a1
            o.z = pack2(A[2], A[3]);   // row lg,  cols 2lq+8,+9    -> a2
            o.w = pack2(A[6], A[7]);   // row lg+8                  -> a3
            jout[jidx(mt16, ch, hl, kt, lane)] = o;
        }
}

// ---------------- fused hidden layer (CTA 64m x 64n, direct-LDG A) ----------------
template<int WRITE_JET>
__global__ __launch_bounds__(256, 2) void k_layer(
    const uint4* __restrict__ jin, uint4* __restrict__ jout,
    const float* __restrict__ W, const float* __restrict__ bias,
    const float* __restrict__ W3)
{
    extern __shared__ __half sm[];
    const int tid = threadIdx.x, lane = tid & 31, wid = tid >> 5;
    const int wm = wid & 3, wn = wid >> 2;
    const int lg = lane >> 2, lq = lane & 3;
    const int t  = lane >> 3, ri = lane & 7;
    const int nt = blockIdx.x & 3, mt = blockIdx.x >> 2;
    const int n0 = nt * 64;
    const int mt16 = mt * 4 + wm;

    const uint32_t smb = smem_u32(sm);
    stage_B(sm, W, n0, 0, tid);

    float acc[3][4][4];
#pragma unroll
    for (int ch = 0; ch < 3; ch++)
#pragma unroll
        for (int nf = 0; nf < 4; nf++)
#pragma unroll
            for (int rr = 0; rr < 4; rr++) acc[ch][nf][rr] = 0.f;

    uint4 abuf[2][6];
    load_A(abuf[0], jin, mt16, 0, lane);
    __syncthreads();   // B half 0 staged

    // ---- 16 k-tiles; per-warp A prefetch; only 2 barriers (B restage) ----
#pragma unroll
    for (int kt = 0; kt < 16; kt++) {
        if (kt == 8) {
            __syncthreads();                 // all warps done reading B half 0
            stage_B(sm, W, n0, 128, tid);
            __syncthreads();
        }
        if (kt < 15) load_A(abuf[(kt + 1) & 1], jin, mt16, kt + 1, lane);

        const int kb = (kt & 7) * 16;
        uint32_t bh[4][2], bl[4][2];
#pragma unroll
        for (int nf = 0; nf < 4; nf++) {
            int n = wn * 32 + nf * 8 + ri;
            uint32_t el = ((t >> 1) ? BLO_E : 0) + n * SB_E + kb + (t & 1) * 8;
            uint32_t rg[4];
            ldsm4(rg, smb + el * 2);
            bh[nf][0] = rg[0]; bh[nf][1] = rg[1];
            bl[nf][0] = rg[2]; bl[nf][1] = rg[3];
        }
        const uint4* a = abuf[kt & 1];
#pragma unroll
        for (int ch = 0; ch < 3; ch++) {
            const uint32_t* ah = (const uint32_t*)&a[ch * 2 + 0];
            const uint32_t* al = (const uint32_t*)&a[ch * 2 + 1];
#pragma unroll
            for (int nf = 0; nf < 4; nf++)
                mma16816(acc[ch][nf], ah, bh[nf]);   // hi*hi
#pragma unroll
            for (int nf = 0; nf < 4; nf++)
                mma16816(acc[ch][nf], ah, bl[nf]);   // hi*lo
#pragma unroll
            for (int nf = 0; nf < 4; nf++)
                mma16816(acc[ch][nf], al, bh[nf]);   // lo*hi
        }
    }

    // ---- epilogue ----
    // e index: e = rh*8 + nf*2 + u  (rh: row lg / lg+8)
    float zz[16], aa[16], cc[16], hh[16];
#pragma unroll
    for (int rh = 0; rh < 2; rh++)
#pragma unroll
        for (int nf = 0; nf < 4; nf++)
#pragma unroll
            for (int u = 0; u < 2; u++) {
                const int e = rh * 8 + nf * 2 + u;
                const int col = n0 + wn * 32 + nf * 8 + lq * 2 + u;
                zz[e] = acc[0][nf][rh * 2 + u] + __ldg(bias + col);
                aa[e] = acc[1][nf][rh * 2 + u];
                cc[e] = acc[2][nf][rh * 2 + u];
            }
    tanh4(zz, hh); tanh4(zz + 4, hh + 4);
    tanh4(zz + 8, hh + 8); tanh4(zz + 12, hh + 12);

    if (WRITE_JET) {
        __half VH[3][16], VL[3][16];
#pragma unroll
        for (int e = 0; e < 16; e++) {
            float h = hh[e];
            float g = fmaf(-h, h, 1.0f);
            float d = g * aa[e];
            float ev = g * fmaf(-2.0f * h * aa[e], aa[e], cc[e]);
            hsplit(h,  VH[0][e], VL[0][e]);
            hsplit(d,  VH[1][e], VL[1][e]);
            hsplit(ev, VH[2][e], VL[2][e]);
        }
        const int ktbase = (n0 + wn * 32) >> 4;
#pragma unroll
        for (int ch = 0; ch < 3; ch++)
#pragma unroll
            for (int hl = 0; hl < 2; hl++) {
                const __half* A = hl ? VL[ch] : VH[ch];
#pragma unroll
                for (int p = 0; p < 2; p++) {
                    uint4 o;
                    o.x = pack2(A[4 * p],         A[4 * p + 1]);       // row lg,  k-lo
                    o.y = pack2(A[8 + 4 * p],     A[8 + 4 * p + 1]);   // row lg+8, k-lo
                    o.z = pack2(A[4 * p + 2],     A[4 * p + 3]);       // row lg,  k-hi
                    o.w = pack2(A[8 + 4 * p + 2], A[8 + 4 * p + 3]);   // row lg+8, k-hi
                    jout[jidx(mt16, ch, hl, ktbase + p, lane)] = o;
                }
            }
    } else {
        float su[2] = {0.f, 0.f}, se[2] = {0.f, 0.f};
#pragma unroll
        for (int rh = 0; rh < 2; rh++)
#pragma unroll
            for (int nf = 0; nf < 4; nf++)
#pragma unroll
                for (int u = 0; u < 2; u++) {
                    const int e = rh * 8 + nf * 2 + u;
                    const int col = n0 + wn * 32 + nf * 8 + lq * 2 + u;
                    float h = hh[e];
                    float g = fmaf(-h, h, 1.0f);
                    float ev = g * fmaf(-2.0f * h * aa[e], aa[e], cc[e]);
                    float w3 = __ldg(W3 + col);
                    su[rh] = fmaf(h, w3, su[rh]);
                    se[rh] = fmaf(ev, w3, se[rh]);
                }
#pragma unroll
        for (int rh = 0; rh < 2; rh++) {
            float s = su[rh];
            s += __shfl_xor_sync(0xffffffffu, s, 1);
            s += __shfl_xor_sync(0xffffffffu, s, 2);
            float v = se[rh];
            v += __shfl_xor_sync(0xffffffffu, v, 1);
            v += __shfl_xor_sync(0xffffffffu, v, 2);
            if (lq == 0) {
                const int row = mt16 * 16 + rh * 8 + lg;
                const int p = nt * 2 + wn;
                g_part[(size_t)row * 16 + p]     = s;
                g_part[(size_t)row * 16 + 8 + p] = v;
            }
        }
    }
}

// ---------------- tiny kernels ----------------
__global__ void k_dummy() {}

__global__ void k_head(const float* __restrict__ x, const float* __restrict__ wts,
                       const float* __restrict__ b3) {
    int i = blockIdx.x * 256 + threadIdx.x;
    const float* p = g_part + (size_t)i * 16;
    float4 a0 = *(const float4*)p,       a1 = *(const float4*)(p + 4);
    float4 a2 = *(const float4*)(p + 8), a3 = *(const float4*)(p + 12);
    float su = ((a0.x + a0.y) + (a0.z + a0.w)) + ((a1.x + a1.y) + (a1.z + a1.w));
    float se = ((a2.x + a2.y) + (a2.z + a2.w)) + ((a3.x + a3.y) + (a3.z + a3.w));
    float xi = x[i];
    g_r[i] = wts[i] * (se + my_sin(PI_F * xi));
    if (i == 0)         g_ub[0] = su + __ldg(b3);
    if (i == N_PTS - 1) g_ub[1] = su + __ldg(b3);
}

__global__ __launch_bounds__(256) void k_spec(const float* __restrict__ x) {
    const int kg  = blockIdx.x >> 3;
    const int seg = blockIdx.x & 7;
    const int k0  = kg * 8;
    const int i0  = seg * 4096;
    float pk[8];
#pragma unroll
    for (int q = 0; q < 8; q++) pk[q] = PI_F * (float)(k0 + 1 + q);
    float acc[8] = {0, 0, 0, 0, 0, 0, 0, 0};
    for (int i = threadIdx.x; i < 4096; i += 256) {
        float xi = x[i0 + i], ri = g_r[i0 + i];
#pragma unroll
        for (int q = 0; q < 8; q++)
            acc[q] = fmaf(my_sin(pk[q] * xi), ri, acc[q]);
    }
    __shared__ float sred[8][8];
    int lane = threadIdx.x & 31, wid = threadIdx.x >> 5;
#pragma unroll
    for (int q = 0; q < 8; q++) {
        float v = acc[q];
#pragma unroll
        for (int o = 16; o; o >>= 1) v += __shfl_down_sync(0xffffffffu, v, o);
        if (lane == 0) sred[q][wid] = v;
    }
    __syncthreads();
    if (threadIdx.x < 8) {
        float s = 0.f;
#pragma unroll
        for (int w = 0; w < 8; w++) s += sred[threadIdx.x][w];
        g_Sp[seg * KTEST + k0 + threadIdx.x] = s;
    }
}

__global__ void k_final(float* __restrict__ out) {
    __shared__ float sred[8];
    float s = 0.f;
    for (int t = threadIdx.x; t < KTEST; t += 256) {
        float v = 0.f;
#pragma unroll
        for (int seg = 0; seg < 8; seg++) v += g_Sp[seg * KTEST + t];
        s = fmaf(v, v, s);
    }
    int lane = threadIdx.x & 31, wid = threadIdx.x >> 5;
#pragma unroll
    for (int o = 16; o; o >>= 1) s += __shfl_down_sync(0xffffffffu, s, o);
    if (lane == 0) sred[wid] = s;
    __syncthreads();
    if (threadIdx.x == 0) {
        float t = 0.f;
#pragma unroll
        for (int w = 0; w < 8; w++) t += sred[w];
        out[0] = t * (1.0f / 1024.0f);
        out[1] = 5.0f * (g_ub[0] * g_ub[0] + g_ub[1] * g_ub[1]);
    }
}

extern "C" void kernel_launch(void* const* d_in, const int* in_sizes, int n_in,
                              void* d_out, int out_size) {
    const float* x   = (const float*)d_in[0];
    const float* wts = (const float*)d_in[1];
    const float* W0  = (const float*)d_in[2];
    const float* b0  = (const float*)d_in[3];
    const float* W1  = (const float*)d_in[4];
    const float* b1  = (const float*)d_in[5];
    const float* W2  = (const float*)d_in[6];
    const float* b2  = (const float*)d_in[7];
    const float* W3  = (const float*)d_in[8];
    const float* b3  = (const float*)d_in[9];

    void *pA = nullptr, *pB = nullptr;
    cudaGetSymbolAddress(&pA, g_jetA);
    cudaGetSymbolAddress(&pB, g_jetB);
    uint4* jA = (uint4*)pA;
    uint4* jB = (uint4*)pB;

    cudaFuncSetAttribute(k_layer<1>, cudaFuncAttributeMaxDynamicSharedMemorySize, SMEM_TOT);
    cudaFuncSetAttribute(k_layer<0>, cudaFuncAttributeMaxDynamicSharedMemorySize, SMEM_TOT);

    k_dummy   <<<1, 32>>>();   // shifts ncu -s window onto a layer kernel
    k_init    <<<4096, 256>>>(x, W0, b0, jA);
    k_layer<1><<<2048, 256, SMEM_TOT>>>(jA, jB, W1, b1, nullptr);
    k_layer<0><<<2048, 256, SMEM_TOT>>>(jB, nullptr, W2, b2, W3);
    k_head    <<<N_PTS / 256, 256>>>(x, wts, b3);
    k_spec    <<<KTEST, 256>>>(x);
    k_final   <<<1, 256>>>((float*)d_out);
}